// round 7
// baseline (speedup 1.0000x reference)
#include <cuda_runtime.h>
#include <math.h>

// Problem constants: x[8, 256, 128, 128] fp32
#define NPLANES 2048
#define HW      16384
#define FULL    0xffffffffu

typedef unsigned long long ull;

// Scratch (no allocations allowed)
__device__ float g_p[NPLANES];    // per-plane mean of x
__device__ float g_cs[NPLANES];   // sum of conv(x) (unscaled, no bias)
__device__ float g_cq[NPLANES];   // sumsq of conv(x)
__device__ float g_a[NPLANES];    // sigmoid attention scales

// ---- packed f32x2 helpers (sm_103a native; ptxas never emits FFMA2 itself) ----
__device__ __forceinline__ ull pack2(float lo, float hi) {
    ull r; asm("mov.b64 %0, {%1, %2};" : "=l"(r) : "f"(lo), "f"(hi)); return r;
}
__device__ __forceinline__ void unpack2(ull p, float& lo, float& hi) {
    asm("mov.b64 {%0, %1}, %2;" : "=f"(lo), "=f"(hi) : "l"(p));
}
__device__ __forceinline__ ull ffma2(ull a, ull b, ull c) {
    ull d; asm("fma.rn.f32x2 %0, %1, %2, %3;" : "=l"(d) : "l"(a), "l"(b), "l"(c)); return d;
}
__device__ __forceinline__ ull add2(ull a, ull b) {
    ull d; asm("add.rn.f32x2 %0, %1, %2;" : "=l"(d) : "l"(a), "l"(b)); return d;
}

// Build 5 packed horizontal pairs for one row from an aligned float4 + shuffles.
// Window values e[0..5] = [lft, x, y, z, w, rgt]; P[k] = {e[k], e[k+1]}.
__device__ __forceinline__ void mkrowp(ull* P, float4 v, int lane) {
    float lft = __shfl_up_sync(FULL, v.w, 1);
    float rgt = __shfl_down_sync(FULL, v.x, 1);
    if (lane == 0)  lft = 0.f;
    if (lane == 31) rgt = 0.f;
    P[0] = pack2(lft, v.x);
    P[1] = pack2(v.x, v.y);
    P[2] = pack2(v.y, v.z);
    P[3] = pack2(v.z, v.w);
    P[4] = pack2(v.w, rgt);
}

// 3x3 conv for 4 outputs as two packed chains: 18 FFMA2 total.
// a01 = outputs {c0, c0+1}, a23 = outputs {c0+2, c0+3}.
__device__ __forceinline__ void conv2x2(const ull* t, const ull* m, const ull* b,
                                         const ull* W2, ull init,
                                         ull& a01, ull& a23) {
    ull s0 = init, s1 = init;
    s0 = ffma2(t[0], W2[0], s0); s1 = ffma2(t[2], W2[0], s1);
    s0 = ffma2(t[1], W2[1], s0); s1 = ffma2(t[3], W2[1], s1);
    s0 = ffma2(t[2], W2[2], s0); s1 = ffma2(t[4], W2[2], s1);
    s0 = ffma2(m[0], W2[3], s0); s1 = ffma2(m[2], W2[3], s1);
    s0 = ffma2(m[1], W2[4], s0); s1 = ffma2(m[3], W2[4], s1);
    s0 = ffma2(m[2], W2[5], s0); s1 = ffma2(m[4], W2[5], s1);
    s0 = ffma2(b[0], W2[6], s0); s1 = ffma2(b[2], W2[6], s1);
    s0 = ffma2(b[1], W2[7], s0); s1 = ffma2(b[3], W2[7], s1);
    s0 = ffma2(b[2], W2[8], s0); s1 = ffma2(b[4], W2[8], s1);
    a01 = s0; a23 = s1;
}

// ---------------------------------------------------------------------------
// K1: one block per plane. Single read of x producing: plane mean AND
// sum/sumsq of conv(x) (unscaled, no bias) via a packed shuffle-conv.
// Warp = 32 lanes x 4 cols = full row; warp w owns rows [16w, 16w+16).
// ---------------------------------------------------------------------------
__global__ void __launch_bounds__(256) stats_kernel(const float* __restrict__ x,
                                                     const float* __restrict__ rw) {
    int plane = blockIdx.x;
    int c = plane & 255;
    int tid = threadIdx.x, lane = tid & 31, rseg = tid >> 5;
    int R0 = rseg * 16;
    const float4* xp = (const float4*)(x + (size_t)plane * HW);

    ull W2[9];
#pragma unroll
    for (int i = 0; i < 9; i++) { float wv = rw[c * 9 + i]; W2[i] = pack2(wv, wv); }

    float psum = 0.f;
    ull csum2 = 0ull, csq2 = 0ull;
    ull P[3][5];
    {
        float4 v = (R0 == 0) ? make_float4(0.f,0.f,0.f,0.f) : xp[(R0 - 1) * 32 + lane];
        mkrowp(P[0], v, lane);
        float4 u = xp[R0 * 32 + lane];
        psum += (u.x + u.y) + (u.z + u.w);
        mkrowp(P[1], u, lane);
    }
#pragma unroll
    for (int i = 0; i < 16; i++) {
        int rn = R0 + i + 1;
        float4 v = (rn > 127) ? make_float4(0.f,0.f,0.f,0.f) : xp[rn * 32 + lane];
        if (i < 15) psum += (v.x + v.y) + (v.z + v.w);   // own rows only
        mkrowp(P[(i + 2) % 3], v, lane);
        ull a01, a23;
        conv2x2(P[i % 3], P[(i + 1) % 3], P[(i + 2) % 3], W2, 0ull, a01, a23);
        csum2 = add2(csum2, a01);
        csum2 = add2(csum2, a23);
        csq2 = ffma2(a01, a01, csq2);
        csq2 = ffma2(a23, a23, csq2);
    }
    float c0, c1, q0, q1;
    unpack2(csum2, c0, c1);
    unpack2(csq2, q0, q1);
    float csum = c0 + c1, csq = q0 + q1;

    // Block reduction of psum / csum / csq
#pragma unroll
    for (int o = 16; o; o >>= 1) {
        psum += __shfl_xor_sync(FULL, psum, o);
        csum += __shfl_xor_sync(FULL, csum, o);
        csq  += __shfl_xor_sync(FULL, csq,  o);
    }
    __shared__ float r0[8], r1[8], r2[8];
    if (lane == 0) { r0[rseg] = psum; r1[rseg] = csum; r2[rseg] = csq; }
    __syncthreads();
    if (tid == 0) {
        float t0 = 0.f, t1 = 0.f, t2 = 0.f;
#pragma unroll
        for (int i = 0; i < 8; i++) { t0 += r0[i]; t1 += r1[i]; t2 += r2[i]; }
        g_p[plane]  = t0 * (1.0f / 16384.0f);
        g_cs[plane] = t1;
        g_cq[plane] = t2;
    }
}

// ---------------------------------------------------------------------------
// K2 (fused SE attention): h = leaky(p @ w1^T); a = sigmoid(h @ w2^T).
// ---------------------------------------------------------------------------
__global__ void __launch_bounds__(256) attn_kernel(const float* __restrict__ w1,
                                                    const float* __restrict__ w2) {
    int b = blockIdx.x;
    __shared__ float ps[256];
    __shared__ float hs[64];
    int tid = threadIdx.x;
    ps[tid] = g_p[b * 256 + tid];
    __syncthreads();
    {
        int j = tid >> 2, part = tid & 3;
        const float* wr = w1 + j * 256 + part * 64;
        const float* pr = ps + part * 64;
        float s = 0.f;
#pragma unroll
        for (int cc = 0; cc < 64; cc++) s = fmaf(pr[cc], wr[cc], s);
        s += __shfl_xor_sync(FULL, s, 1);
        s += __shfl_xor_sync(FULL, s, 2);
        if (part == 0) hs[j] = (s > 0.f) ? s : 0.01f * s;
    }
    __syncthreads();
    {
        const float* wr = w2 + tid * 64;
        float s = 0.f;
#pragma unroll
        for (int j = 0; j < 64; j++) s = fmaf(hs[j], wr[j], s);
        g_a[b * 256 + tid] = 1.0f / (1.0f + expf(-s));
    }
}

// ---------------------------------------------------------------------------
// K3: one block per plane, reverse order (ride K1's L2 tail). Single conv
// pass with a-prescaled weights; InstanceNorm stats analytic:
//   mu_y = a*mu_c + b,  var_y = a^2*var_c.
// x read with __ldcs (last use), out stored with __stcs (never re-read).
// ---------------------------------------------------------------------------
__global__ void __launch_bounds__(256) main_kernel(const float* __restrict__ x,
                                                    const float* __restrict__ rw,
                                                    const float* __restrict__ rb,
                                                    float* __restrict__ out) {
    int bc = (NPLANES - 1) - blockIdx.x;
    int c = bc & 255;
    int tid = threadIdx.x, lane = tid & 31, rseg = tid >> 5;
    int R0 = rseg * 16;
    const float4* xp = (const float4*)(x + (size_t)bc * HW);
    float4* op = (float4*)(out + (size_t)bc * HW);

    float a = g_a[bc];
    float bias = rb[c];
    float mu_c  = g_cs[bc] * (1.0f / 16384.0f);
    float var_c = g_cq[bc] * (1.0f / 16384.0f) - mu_c * mu_c;
    float mu   = a * mu_c + bias;
    float rstd = rsqrtf(a * a * var_c + 1e-5f);

    ull W2[9];
#pragma unroll
    for (int i = 0; i < 9; i++) { float wv = a * rw[c * 9 + i]; W2[i] = pack2(wv, wv); }
    ull bias2 = pack2(bias, bias);
    ull rstd2 = pack2(rstd, rstd);
    float nmr = -mu * rstd;
    ull nmr2 = pack2(nmr, nmr);

    ull P[3][5];
    {
        float4 v = (R0 == 0) ? make_float4(0.f,0.f,0.f,0.f) : __ldcs(xp + (R0 - 1) * 32 + lane);
        mkrowp(P[0], v, lane);
        float4 u = __ldcs(xp + R0 * 32 + lane);
        mkrowp(P[1], u, lane);
    }
#pragma unroll
    for (int i = 0; i < 16; i++) {
        int rn = R0 + i + 1;
        float4 v = (rn > 127) ? make_float4(0.f,0.f,0.f,0.f) : __ldcs(xp + rn * 32 + lane);
        mkrowp(P[(i + 2) % 3], v, lane);
        ull a01, a23;
        conv2x2(P[i % 3], P[(i + 1) % 3], P[(i + 2) % 3], W2, bias2, a01, a23);
        // packed normalize: t = s*rstd - mu*rstd
        a01 = ffma2(a01, rstd2, nmr2);
        a23 = ffma2(a23, rstd2, nmr2);
        float4 o;
        unpack2(a01, o.x, o.y);
        unpack2(a23, o.z, o.w);
        o.x = fmaxf(o.x, 0.01f * o.x);
        o.y = fmaxf(o.y, 0.01f * o.y);
        o.z = fmaxf(o.z, 0.01f * o.z);
        o.w = fmaxf(o.w, 0.01f * o.w);
        __stcs(op + (R0 + i) * 32 + lane, o);
    }
}

// ---------------------------------------------------------------------------
extern "C" void kernel_launch(void* const* d_in, const int* in_sizes, int n_in,
                              void* d_out, int out_size) {
    const float* x  = (const float*)d_in[0];
    const float* w1 = (const float*)d_in[1];   // [64, 256]
    const float* w2 = (const float*)d_in[2];   // [256, 64]
    const float* rw = (const float*)d_in[3];   // [256, 1, 3, 3]
    const float* rb = (const float*)d_in[4];   // [256]
    float* out = (float*)d_out;

    stats_kernel<<<NPLANES, 256>>>(x, rw);
    attn_kernel<<<8, 256>>>(w1, w2);
    main_kernel<<<NPLANES, 256>>>(x, rw, rb, out);
}

// round 8
// speedup vs baseline: 1.0659x; 1.0659x over previous
#include <cuda_runtime.h>
#include <math.h>

// Problem constants: x[8, 256, 128, 128] fp32
#define NPLANES 2048
#define HW      16384
#define FULL    0xffffffffu

// Scratch (no allocations allowed)
__device__ float g_p[NPLANES];    // per-plane mean of x
__device__ float g_cs[NPLANES];   // sum of conv(x) (unscaled, no bias)
__device__ float g_cq[NPLANES];   // sumsq of conv(x)
__device__ float g_a[NPLANES];    // sigmoid attention scales
__device__ float g_zero = 0.f;    // halo redirect target

// Build a 6-float window row from an aligned float4 + warp shuffles (stats).
__device__ __forceinline__ void mkrow(float* e, float4 v, int lane) {
    float lft = __shfl_up_sync(FULL, v.w, 1);
    float rgt = __shfl_down_sync(FULL, v.x, 1);
    if (lane == 0)  lft = 0.f;
    if (lane == 31) rgt = 0.f;
    e[0] = lft; e[1] = v.x; e[2] = v.y; e[3] = v.z; e[4] = v.w; e[5] = rgt;
}

__device__ __forceinline__ float conv4(const float* et, const float* em,
                                        const float* eb, const float* w,
                                        float init, int j) {
    float s = init;
    s = fmaf(et[j], w[0], s); s = fmaf(et[j+1], w[1], s); s = fmaf(et[j+2], w[2], s);
    s = fmaf(em[j], w[3], s); s = fmaf(em[j+1], w[4], s); s = fmaf(em[j+2], w[5], s);
    s = fmaf(eb[j], w[6], s); s = fmaf(eb[j+1], w[7], s); s = fmaf(eb[j+2], w[8], s);
    return s;
}

// ---------------------------------------------------------------------------
// K1: one block per plane. Single read of x producing: plane mean AND
// sum/sumsq of conv(x) (unscaled, no bias) via a rolling shuffle-conv.
// (Unchanged from the 84.0us version — proven.)
// ---------------------------------------------------------------------------
__global__ void __launch_bounds__(256) stats_kernel(const float* __restrict__ x,
                                                     const float* __restrict__ rw) {
    int plane = blockIdx.x;
    int c = plane & 255;
    int tid = threadIdx.x, lane = tid & 31, rseg = tid >> 5;
    int R0 = rseg * 16;
    const float4* xp = (const float4*)(x + (size_t)plane * HW);

    float w[9];
#pragma unroll
    for (int i = 0; i < 9; i++) w[i] = rw[c * 9 + i];

    float psum = 0.f, csum = 0.f, csq = 0.f;
    float e[3][6];
    {
        float4 v = (R0 == 0) ? make_float4(0.f,0.f,0.f,0.f) : xp[(R0 - 1) * 32 + lane];
        mkrow(e[0], v, lane);
        float4 u = xp[R0 * 32 + lane];
        psum += (u.x + u.y) + (u.z + u.w);
        mkrow(e[1], u, lane);
    }
#pragma unroll
    for (int i = 0; i < 16; i++) {
        int rn = R0 + i + 1;
        float4 v = (rn > 127) ? make_float4(0.f,0.f,0.f,0.f) : xp[rn * 32 + lane];
        if (i < 15) psum += (v.x + v.y) + (v.z + v.w);   // own rows only
        mkrow(e[(i + 2) % 3], v, lane);
        const float* et = e[i % 3];
        const float* em = e[(i + 1) % 3];
        const float* eb = e[(i + 2) % 3];
#pragma unroll
        for (int j = 0; j < 4; j++) {
            float s = conv4(et, em, eb, w, 0.f, j);
            csum += s;
            csq = fmaf(s, s, csq);
        }
    }

#pragma unroll
    for (int o = 16; o; o >>= 1) {
        psum += __shfl_xor_sync(FULL, psum, o);
        csum += __shfl_xor_sync(FULL, csum, o);
        csq  += __shfl_xor_sync(FULL, csq,  o);
    }
    __shared__ float r0[8], r1[8], r2[8];
    if (lane == 0) { r0[rseg] = psum; r1[rseg] = csum; r2[rseg] = csq; }
    __syncthreads();
    if (tid == 0) {
        float t0 = 0.f, t1 = 0.f, t2 = 0.f;
#pragma unroll
        for (int i = 0; i < 8; i++) { t0 += r0[i]; t1 += r1[i]; t2 += r2[i]; }
        g_p[plane]  = t0 * (1.0f / 16384.0f);
        g_cs[plane] = t1;
        g_cq[plane] = t2;
    }
}

// ---------------------------------------------------------------------------
// K2 (fused SE attention): h = leaky(p @ w1^T); a = sigmoid(h @ w2^T).
// ---------------------------------------------------------------------------
__global__ void __launch_bounds__(256) attn_kernel(const float* __restrict__ w1,
                                                    const float* __restrict__ w2) {
    int b = blockIdx.x;
    __shared__ float ps[256];
    __shared__ float hs[64];
    int tid = threadIdx.x;
    ps[tid] = g_p[b * 256 + tid];
    __syncthreads();
    {
        int j = tid >> 2, part = tid & 3;
        const float* wr = w1 + j * 256 + part * 64;
        const float* pr = ps + part * 64;
        float s = 0.f;
#pragma unroll
        for (int cc = 0; cc < 64; cc++) s = fmaf(pr[cc], wr[cc], s);
        s += __shfl_xor_sync(FULL, s, 1);
        s += __shfl_xor_sync(FULL, s, 2);
        if (part == 0) hs[j] = (s > 0.f) ? s : 0.01f * s;
    }
    __syncthreads();
    {
        const float* wr = w2 + tid * 64;
        float s = 0.f;
#pragma unroll
        for (int j = 0; j < 64; j++) s = fmaf(hs[j], wr[j], s);
        g_a[b * 256 + tid] = 1.0f / (1.0f + expf(-s));
    }
}

// ---------------------------------------------------------------------------
// K3: one block per plane, reverse order (ride K1's L2 tail). Single conv
// pass with FULLY FOLDED weights: w' = a*rstd*w, c' = (bias-mu)*rstd, so the
// conv output is already normalized — epilogue is just leaky relu.
// Halo exchange via zero-redirected __ldg (no SHFL, no per-row selects):
// lanes 0/31 point their halo pointer at g_zero with step 0.
// x read with __ldcs (last use), out stored with __stcs (never re-read).
// ---------------------------------------------------------------------------
__global__ void __launch_bounds__(256) main_kernel(const float* __restrict__ x,
                                                    const float* __restrict__ rw,
                                                    const float* __restrict__ rb,
                                                    float* __restrict__ out) {
    int bc = (NPLANES - 1) - blockIdx.x;
    int c = bc & 255;
    int tid = threadIdx.x, lane = tid & 31, rseg = tid >> 5;
    int R0 = rseg * 16;
    const float* xbase = x + (size_t)bc * HW;
    const float4* xp = (const float4*)xbase;
    float4* op = (float4*)(out + (size_t)bc * HW);

    float a = g_a[bc];
    float bias = rb[c];
    float mu_c  = g_cs[bc] * (1.0f / 16384.0f);
    float var_c = g_cq[bc] * (1.0f / 16384.0f) - mu_c * mu_c;
    float mu   = a * mu_c + bias;
    float rstd = rsqrtf(a * a * var_c + 1e-5f);
    float scale = a * rstd;               // fold a and rstd into weights
    float init = (bias - mu) * rstd;      // folded bias + normalization shift

    float w[9];
#pragma unroll
    for (int i = 0; i < 9; i++) w[i] = scale * rw[c * 9 + i];

    // Halo pointers with zero-redirect (no per-row predication)
    const float* lp = (lane == 0)  ? &g_zero : (xbase + (R0 - 1) * 128 + lane * 4 - 1);
    const float* rp = (lane == 31) ? &g_zero : (xbase + (R0 - 1) * 128 + lane * 4 + 4);
    int ls = (lane == 0)  ? 0 : 128;
    int rs = (lane == 31) ? 0 : 128;

    float e[3][6];
    if (R0 == 0) {
#pragma unroll
        for (int j = 0; j < 6; j++) e[0][j] = 0.f;
    } else {
        float4 v = __ldcs(xp + (R0 - 1) * 32 + lane);
        e[0][0] = __ldg(lp); e[0][1] = v.x; e[0][2] = v.y;
        e[0][3] = v.z; e[0][4] = v.w; e[0][5] = __ldg(rp);
    }
    lp += ls; rp += rs;
    {
        float4 v = __ldcs(xp + R0 * 32 + lane);
        e[1][0] = __ldg(lp); e[1][1] = v.x; e[1][2] = v.y;
        e[1][3] = v.z; e[1][4] = v.w; e[1][5] = __ldg(rp);
    }
    lp += ls; rp += rs;

#pragma unroll
    for (int i = 0; i < 16; i++) {
        int rn = R0 + i + 1;
        float* en = e[(i + 2) % 3];
        if (rn <= 127) {
            float4 v = __ldcs(xp + rn * 32 + lane);
            en[0] = __ldg(lp); en[1] = v.x; en[2] = v.y;
            en[3] = v.z; en[4] = v.w; en[5] = __ldg(rp);
        } else {
#pragma unroll
            for (int j = 0; j < 6; j++) en[j] = 0.f;
        }
        lp += ls; rp += rs;

        const float* et = e[i % 3];
        const float* em = e[(i + 1) % 3];
        const float* eb = en;
        float4 o;
        float* opn = (float*)&o;
#pragma unroll
        for (int j = 0; j < 4; j++) {
            float t = conv4(et, em, eb, w, init, j);   // already normalized
            opn[j] = fmaxf(t, 0.01f * t);               // leaky relu
        }
        __stcs(op + (R0 + i) * 32 + lane, o);
    }
}

// ---------------------------------------------------------------------------
extern "C" void kernel_launch(void* const* d_in, const int* in_sizes, int n_in,
                              void* d_out, int out_size) {
    const float* x  = (const float*)d_in[0];
    const float* w1 = (const float*)d_in[1];   // [64, 256]
    const float* w2 = (const float*)d_in[2];   // [256, 64]
    const float* rw = (const float*)d_in[3];   // [256, 1, 3, 3]
    const float* rb = (const float*)d_in[4];   // [256]
    float* out = (float*)d_out;

    stats_kernel<<<NPLANES, 256>>>(x, rw);
    attn_kernel<<<8, 256>>>(w1, w2);
    main_kernel<<<NPLANES, 256>>>(x, rw, rb, out);
}

// round 9
// speedup vs baseline: 1.1012x; 1.0331x over previous
#include <cuda_runtime.h>
#include <math.h>

// Problem constants: x[8, 256, 128, 128] fp32
#define NPLANES 2048
#define HW      16384
#define FULL    0xffffffffu

// Scratch (no allocations allowed). Two slots per plane (half 0 / half 1).
__device__ float g_p [2 * NPLANES];   // partial sum of x
__device__ float g_cs[2 * NPLANES];   // partial sum of conv(x) (unscaled, no bias)
__device__ float g_cq[2 * NPLANES];   // partial sumsq of conv(x)
__device__ float g_a [NPLANES];       // sigmoid attention scales

// Build a 6-float window row from an aligned float4 + warp shuffles.
__device__ __forceinline__ void mkrow(float* e, float4 v, int lane) {
    float lft = __shfl_up_sync(FULL, v.w, 1);
    float rgt = __shfl_down_sync(FULL, v.x, 1);
    if (lane == 0)  lft = 0.f;
    if (lane == 31) rgt = 0.f;
    e[0] = lft; e[1] = v.x; e[2] = v.y; e[3] = v.z; e[4] = v.w; e[5] = rgt;
}

__device__ __forceinline__ float conv4(const float* et, const float* em,
                                        const float* eb, const float* w,
                                        float init, int j) {
    float s = init;
    s = fmaf(et[j], w[0], s); s = fmaf(et[j+1], w[1], s); s = fmaf(et[j+2], w[2], s);
    s = fmaf(em[j], w[3], s); s = fmaf(em[j+1], w[4], s); s = fmaf(em[j+2], w[5], s);
    s = fmaf(eb[j], w[6], s); s = fmaf(eb[j+1], w[7], s); s = fmaf(eb[j+2], w[8], s);
    return s;
}

// ---------------------------------------------------------------------------
// K1: TWO blocks per plane (half-planes of 64 rows) -> grid 4096 for better
// wave quantization. Each block: partial sum of x, partial sum/sumsq of
// conv(x) (unscaled, no bias) via the rolling shuffle-conv.
// Warp covers rows [R0, R0+8); strip halo rows read directly from x.
// ---------------------------------------------------------------------------
__global__ void __launch_bounds__(256) stats_kernel(const float* __restrict__ x,
                                                     const float* __restrict__ rw) {
    int plane = blockIdx.x >> 1, half = blockIdx.x & 1;
    int c = plane & 255;
    int tid = threadIdx.x, lane = tid & 31, rseg = tid >> 5;
    int R0 = half * 64 + rseg * 8;
    const float4* xp = (const float4*)(x + (size_t)plane * HW);

    float w[9];
#pragma unroll
    for (int i = 0; i < 9; i++) w[i] = rw[c * 9 + i];

    float psum = 0.f, csum = 0.f, csq = 0.f;
    float e[3][6];
    {
        float4 v = (R0 == 0) ? make_float4(0.f,0.f,0.f,0.f) : xp[(R0 - 1) * 32 + lane];
        mkrow(e[0], v, lane);
        float4 u = xp[R0 * 32 + lane];
        psum += (u.x + u.y) + (u.z + u.w);
        mkrow(e[1], u, lane);
    }
#pragma unroll
    for (int i = 0; i < 8; i++) {
        int rn = R0 + i + 1;
        float4 v = (rn > 127) ? make_float4(0.f,0.f,0.f,0.f) : xp[rn * 32 + lane];
        if (i < 7) psum += (v.x + v.y) + (v.z + v.w);   // own 8 rows only
        mkrow(e[(i + 2) % 3], v, lane);
        const float* et = e[i % 3];
        const float* em = e[(i + 1) % 3];
        const float* eb = e[(i + 2) % 3];
#pragma unroll
        for (int j = 0; j < 4; j++) {
            float s = conv4(et, em, eb, w, 0.f, j);
            csum += s;
            csq = fmaf(s, s, csq);
        }
    }

#pragma unroll
    for (int o = 16; o; o >>= 1) {
        psum += __shfl_xor_sync(FULL, psum, o);
        csum += __shfl_xor_sync(FULL, csum, o);
        csq  += __shfl_xor_sync(FULL, csq,  o);
    }
    __shared__ float r0[8], r1[8], r2[8];
    if (lane == 0) { r0[rseg] = psum; r1[rseg] = csum; r2[rseg] = csq; }
    __syncthreads();
    if (tid == 0) {
        float t0 = 0.f, t1 = 0.f, t2 = 0.f;
#pragma unroll
        for (int i = 0; i < 8; i++) { t0 += r0[i]; t1 += r1[i]; t2 += r2[i]; }
        int slot = half * NPLANES + plane;
        g_p[slot]  = t0;
        g_cs[slot] = t1;
        g_cq[slot] = t2;
    }
}

// ---------------------------------------------------------------------------
// K2 (fused SE attention): h = leaky(p @ w1^T); a = sigmoid(h @ w2^T).
// ---------------------------------------------------------------------------
__global__ void __launch_bounds__(256) attn_kernel(const float* __restrict__ w1,
                                                    const float* __restrict__ w2) {
    int b = blockIdx.x;
    __shared__ float ps[256];
    __shared__ float hs[64];
    int tid = threadIdx.x;
    int pl = b * 256 + tid;
    ps[tid] = (g_p[pl] + g_p[NPLANES + pl]) * (1.0f / 16384.0f);
    __syncthreads();
    {
        int j = tid >> 2, part = tid & 3;
        const float* wr = w1 + j * 256 + part * 64;
        const float* pr = ps + part * 64;
        float s = 0.f;
#pragma unroll
        for (int cc = 0; cc < 64; cc++) s = fmaf(pr[cc], wr[cc], s);
        s += __shfl_xor_sync(FULL, s, 1);
        s += __shfl_xor_sync(FULL, s, 2);
        if (part == 0) hs[j] = (s > 0.f) ? s : 0.01f * s;
    }
    __syncthreads();
    {
        const float* wr = w2 + tid * 64;
        float s = 0.f;
#pragma unroll
        for (int j = 0; j < 64; j++) s = fmaf(hs[j], wr[j], s);
        g_a[b * 256 + tid] = 1.0f / (1.0f + expf(-s));
    }
}

// ---------------------------------------------------------------------------
// K3: TWO blocks per plane (64 rows each), reverse order (ride K1's L2 tail).
// Single conv pass with FULLY FOLDED weights: w' = a*rstd*w,
// init = (bias-mu)*rstd -> conv output is already normalized; epilogue is
// just leaky relu. SHFL halo (proven cheapest). __ldcs reads, __stcs stores.
// ---------------------------------------------------------------------------
__global__ void __launch_bounds__(256) main_kernel(const float* __restrict__ x,
                                                    const float* __restrict__ rw,
                                                    const float* __restrict__ rb,
                                                    float* __restrict__ out) {
    int idx = (2 * NPLANES - 1) - blockIdx.x;
    int bc = idx >> 1, half = idx & 1;
    int c = bc & 255;
    int tid = threadIdx.x, lane = tid & 31, rseg = tid >> 5;
    int R0 = half * 64 + rseg * 8;
    const float4* xp = (const float4*)(x + (size_t)bc * HW);
    float4* op = (float4*)(out + (size_t)bc * HW);

    float a = g_a[bc];
    float bias = rb[c];
    float csum = g_cs[bc] + g_cs[NPLANES + bc];
    float csq  = g_cq[bc] + g_cq[NPLANES + bc];
    float mu_c  = csum * (1.0f / 16384.0f);
    float var_c = csq * (1.0f / 16384.0f) - mu_c * mu_c;
    float mu   = a * mu_c + bias;
    float rstd = rsqrtf(a * a * var_c + 1e-5f);
    float scale = a * rstd;
    float init = (bias - mu) * rstd;

    float w[9];
#pragma unroll
    for (int i = 0; i < 9; i++) w[i] = scale * rw[c * 9 + i];

    float e[3][6];
    {
        float4 v = (R0 == 0) ? make_float4(0.f,0.f,0.f,0.f) : __ldcs(xp + (R0 - 1) * 32 + lane);
        mkrow(e[0], v, lane);
        float4 u = __ldcs(xp + R0 * 32 + lane);
        mkrow(e[1], u, lane);
    }
#pragma unroll
    for (int i = 0; i < 8; i++) {
        int rn = R0 + i + 1;
        float4 v = (rn > 127) ? make_float4(0.f,0.f,0.f,0.f) : __ldcs(xp + rn * 32 + lane);
        mkrow(e[(i + 2) % 3], v, lane);
        const float* et = e[i % 3];
        const float* em = e[(i + 1) % 3];
        const float* eb = e[(i + 2) % 3];
        float4 o;
        float* opn = (float*)&o;
#pragma unroll
        for (int j = 0; j < 4; j++) {
            float t = conv4(et, em, eb, w, init, j);   // already normalized
            opn[j] = fmaxf(t, 0.01f * t);
        }
        __stcs(op + (R0 + i) * 32 + lane, o);
    }
}

// ---------------------------------------------------------------------------
extern "C" void kernel_launch(void* const* d_in, const int* in_sizes, int n_in,
                              void* d_out, int out_size) {
    const float* x  = (const float*)d_in[0];
    const float* w1 = (const float*)d_in[1];   // [64, 256]
    const float* w2 = (const float*)d_in[2];   // [256, 64]
    const float* rw = (const float*)d_in[3];   // [256, 1, 3, 3]
    const float* rb = (const float*)d_in[4];   // [256]
    float* out = (float*)d_out;

    stats_kernel<<<2 * NPLANES, 256>>>(x, rw);
    attn_kernel<<<8, 256>>>(w1, w2);
    main_kernel<<<2 * NPLANES, 256>>>(x, rw, rb, out);
}

// round 10
// speedup vs baseline: 1.1342x; 1.0299x over previous
#include <cuda_runtime.h>
#include <math.h>

// Problem constants: x[8, 256, 128, 128] fp32
#define NPLANES 2048
#define HW      16384
#define FULL    0xffffffffu

// Scratch (no allocations allowed). Two slots per plane for stats halves.
__device__ float g_p [2 * NPLANES];   // partial sum of x
__device__ float g_cs[2 * NPLANES];   // partial sum of conv(x) (unscaled)
__device__ float g_cq[2 * NPLANES];   // partial sumsq of conv(x)
__device__ float g_a [NPLANES];       // sigmoid attention scales

// Build a 6-float window row from an aligned float4 + warp shuffles.
__device__ __forceinline__ void mkrow(float* e, float4 v, int lane) {
    float lft = __shfl_up_sync(FULL, v.w, 1);
    float rgt = __shfl_down_sync(FULL, v.x, 1);
    if (lane == 0)  lft = 0.f;
    if (lane == 31) rgt = 0.f;
    e[0] = lft; e[1] = v.x; e[2] = v.y; e[3] = v.z; e[4] = v.w; e[5] = rgt;
}

__device__ __forceinline__ float conv4(const float* et, const float* em,
                                        const float* eb, const float* w,
                                        float init, int j) {
    float s = init;
    s = fmaf(et[j], w[0], s); s = fmaf(et[j+1], w[1], s); s = fmaf(et[j+2], w[2], s);
    s = fmaf(em[j], w[3], s); s = fmaf(em[j+1], w[4], s); s = fmaf(em[j+2], w[5], s);
    s = fmaf(eb[j], w[6], s); s = fmaf(eb[j+1], w[7], s); s = fmaf(eb[j+2], w[8], s);
    return s;
}

__device__ __forceinline__ float4 zero4() { return make_float4(0.f, 0.f, 0.f, 0.f); }

// ---------------------------------------------------------------------------
// K1: TWO blocks per plane (half-planes of 64 rows). Partial sum of x +
// partial sum/sumsq of conv(x) (unscaled, no bias), rolling shuffle-conv with
// an explicit 2-row LOAD PREFETCH pipeline (2-3 LDGs in flight per warp).
// ---------------------------------------------------------------------------
__global__ void __launch_bounds__(256) stats_kernel(const float* __restrict__ x,
                                                     const float* __restrict__ rw) {
    int plane = blockIdx.x >> 1, half = blockIdx.x & 1;
    int c = plane & 255;
    int tid = threadIdx.x, lane = tid & 31, rseg = tid >> 5;
    int R0 = half * 64 + rseg * 8;
    const float4* xp = (const float4*)(x + (size_t)plane * HW);

    float w[9];
#pragma unroll
    for (int i = 0; i < 9; i++) w[i] = rw[c * 9 + i];

    // Issue the first 4 row loads back-to-back (MLP), then build windows.
    float4 vm1 = (R0 == 0) ? zero4() : xp[(R0 - 1) * 32 + lane];
    float4 v0  = xp[R0 * 32 + lane];
    float4 p0  = xp[(R0 + 1) * 32 + lane];              // consumed at i=0
    float4 p1  = xp[(R0 + 2) * 32 + lane];              // consumed at i=1

    float psum = (v0.x + v0.y) + (v0.z + v0.w);
    float csum = 0.f, csq = 0.f;
    float e[3][6];
    mkrow(e[0], vm1, lane);
    mkrow(e[1], v0, lane);

#pragma unroll
    for (int i = 0; i < 8; i++) {
        float4 v = p0;
        p0 = p1;
        // prefetch row consumed at i+2 (rows R0+3 .. R0+8)
        if (i < 6) {
            int rp = R0 + i + 3;
            p1 = (rp > 127) ? zero4() : xp[rp * 32 + lane];
        }
        if (i < 7) psum += (v.x + v.y) + (v.z + v.w);   // own rows R0+1..R0+7
        mkrow(e[(i + 2) % 3], v, lane);
        const float* et = e[i % 3];
        const float* em = e[(i + 1) % 3];
        const float* eb = e[(i + 2) % 3];
#pragma unroll
        for (int j = 0; j < 4; j++) {
            float s = conv4(et, em, eb, w, 0.f, j);
            csum += s;
            csq = fmaf(s, s, csq);
        }
    }

#pragma unroll
    for (int o = 16; o; o >>= 1) {
        psum += __shfl_xor_sync(FULL, psum, o);
        csum += __shfl_xor_sync(FULL, csum, o);
        csq  += __shfl_xor_sync(FULL, csq,  o);
    }
    __shared__ float r0[8], r1[8], r2[8];
    if (lane == 0) { r0[rseg] = psum; r1[rseg] = csum; r2[rseg] = csq; }
    __syncthreads();
    if (tid == 0) {
        float t0 = 0.f, t1 = 0.f, t2 = 0.f;
#pragma unroll
        for (int i = 0; i < 8; i++) { t0 += r0[i]; t1 += r1[i]; t2 += r2[i]; }
        int slot = half * NPLANES + plane;
        g_p[slot]  = t0;
        g_cs[slot] = t1;
        g_cq[slot] = t2;
    }
}

// ---------------------------------------------------------------------------
// K2 (fused SE attention): h = leaky(p @ w1^T); a = sigmoid(h @ w2^T).
// ---------------------------------------------------------------------------
__global__ void __launch_bounds__(256) attn_kernel(const float* __restrict__ w1,
                                                    const float* __restrict__ w2) {
    int b = blockIdx.x;
    __shared__ float ps[256];
    __shared__ float hs[64];
    int tid = threadIdx.x;
    int pl = b * 256 + tid;
    ps[tid] = (g_p[pl] + g_p[NPLANES + pl]) * (1.0f / 16384.0f);
    __syncthreads();
    {
        int j = tid >> 2, part = tid & 3;
        const float* wr = w1 + j * 256 + part * 64;
        const float* pr = ps + part * 64;
        float s = 0.f;
#pragma unroll
        for (int cc = 0; cc < 64; cc++) s = fmaf(pr[cc], wr[cc], s);
        s += __shfl_xor_sync(FULL, s, 1);
        s += __shfl_xor_sync(FULL, s, 2);
        if (part == 0) hs[j] = (s > 0.f) ? s : 0.01f * s;
    }
    __syncthreads();
    {
        const float* wr = w2 + tid * 64;
        float s = 0.f;
#pragma unroll
        for (int j = 0; j < 64; j++) s = fmaf(hs[j], wr[j], s);
        g_a[b * 256 + tid] = 1.0f / (1.0f + expf(-s));
    }
}

// ---------------------------------------------------------------------------
// K3: ONE block per plane (full 128 rows — better L2 locality than halves),
// reverse order to ride K1's L2 tail. Single conv pass with FULLY FOLDED
// weights: w' = a*rstd*w, init = (bias-mu)*rstd -> output of conv is already
// normalized; epilogue = leaky relu only. SHFL halo. 2-row load prefetch
// pipeline. __ldcs reads (last use), __stcs stores (never re-read).
// ---------------------------------------------------------------------------
__global__ void __launch_bounds__(256) main_kernel(const float* __restrict__ x,
                                                    const float* __restrict__ rw,
                                                    const float* __restrict__ rb,
                                                    float* __restrict__ out) {
    int bc = (NPLANES - 1) - blockIdx.x;
    int c = bc & 255;
    int tid = threadIdx.x, lane = tid & 31, rseg = tid >> 5;
    int R0 = rseg * 16;
    const float4* xp = (const float4*)(x + (size_t)bc * HW);
    float4* op = (float4*)(out + (size_t)bc * HW);

    float a = g_a[bc];
    float bias = rb[c];
    float csum = g_cs[bc] + g_cs[NPLANES + bc];
    float csq  = g_cq[bc] + g_cq[NPLANES + bc];
    float mu_c  = csum * (1.0f / 16384.0f);
    float var_c = csq * (1.0f / 16384.0f) - mu_c * mu_c;
    float mu   = a * mu_c + bias;
    float rstd = rsqrtf(a * a * var_c + 1e-5f);
    float scale = a * rstd;
    float init = (bias - mu) * rstd;

    float w[9];
#pragma unroll
    for (int i = 0; i < 9; i++) w[i] = scale * rw[c * 9 + i];

    float4 vm1 = (R0 == 0) ? zero4() : __ldcs(xp + (R0 - 1) * 32 + lane);
    float4 v0  = __ldcs(xp + R0 * 32 + lane);
    float4 p0  = __ldcs(xp + (R0 + 1) * 32 + lane);     // consumed at i=0
    float4 p1  = __ldcs(xp + (R0 + 2) * 32 + lane);     // consumed at i=1

    float e[3][6];
    mkrow(e[0], vm1, lane);
    mkrow(e[1], v0, lane);

#pragma unroll
    for (int i = 0; i < 16; i++) {
        float4 v = p0;
        p0 = p1;
        if (i < 14) {
            int rp = R0 + i + 3;
            p1 = (rp > 127) ? zero4() : __ldcs(xp + rp * 32 + lane);
        }
        mkrow(e[(i + 2) % 3], v, lane);
        const float* et = e[i % 3];
        const float* em = e[(i + 1) % 3];
        const float* eb = e[(i + 2) % 3];
        float4 o;
        float* opn = (float*)&o;
#pragma unroll
        for (int j = 0; j < 4; j++) {
            float t = conv4(et, em, eb, w, init, j);   // already normalized
            opn[j] = fmaxf(t, 0.01f * t);
        }
        __stcs(op + (R0 + i) * 32 + lane, o);
    }
}

// ---------------------------------------------------------------------------
extern "C" void kernel_launch(void* const* d_in, const int* in_sizes, int n_in,
                              void* d_out, int out_size) {
    const float* x  = (const float*)d_in[0];
    const float* w1 = (const float*)d_in[1];   // [64, 256]
    const float* w2 = (const float*)d_in[2];   // [256, 64]
    const float* rw = (const float*)d_in[3];   // [256, 1, 3, 3]
    const float* rb = (const float*)d_in[4];   // [256]
    float* out = (float*)d_out;

    stats_kernel<<<2 * NPLANES, 256>>>(x, rw);
    attn_kernel<<<8, 256>>>(w1, w2);
    main_kernel<<<NPLANES, 256>>>(x, rw, rb, out);
}

// round 11
// speedup vs baseline: 1.1451x; 1.0097x over previous
#include <cuda_runtime.h>
#include <math.h>

// Problem constants: x[8, 256, 128, 128] fp32
#define NPLANES 2048
#define HW      16384
#define FULL    0xffffffffu

// Scratch (no allocations allowed). Two slots per plane (half 0 / half 1).
__device__ float g_p [2 * NPLANES];   // partial sum of x
__device__ float g_cs[2 * NPLANES];   // partial sum of conv(x) (unscaled)
__device__ float g_cq[2 * NPLANES];   // partial sumsq of conv(x)
__device__ float g_a [NPLANES];       // sigmoid attention scales

__device__ __forceinline__ float4 zero4() { return make_float4(0.f, 0.f, 0.f, 0.f); }

// Halo scalars for one row held as a float4 across the warp.
__device__ __forceinline__ float halo_l(float4 v, int lane) {
    float l = __shfl_up_sync(FULL, v.w, 1);
    return (lane == 0) ? 0.f : l;
}
__device__ __forceinline__ float halo_r(float4 v, int lane) {
    float r = __shfl_down_sync(FULL, v.x, 1);
    return (lane == 31) ? 0.f : r;
}

// 3x3 conv producing 4 outputs, reading float4 rows + halo scalars directly.
__device__ __forceinline__ float4 conv_row(float4 t, float tl, float tr,
                                            float4 m, float ml, float mr,
                                            float4 b, float bl, float br,
                                            const float* w, float init) {
    float4 o;
    o.x = init; o.y = init; o.z = init; o.w = init;
    o.x = fmaf(tl,  w[0], o.x); o.x = fmaf(t.x, w[1], o.x); o.x = fmaf(t.y, w[2], o.x);
    o.y = fmaf(t.x, w[0], o.y); o.y = fmaf(t.y, w[1], o.y); o.y = fmaf(t.z, w[2], o.y);
    o.z = fmaf(t.y, w[0], o.z); o.z = fmaf(t.z, w[1], o.z); o.z = fmaf(t.w, w[2], o.z);
    o.w = fmaf(t.z, w[0], o.w); o.w = fmaf(t.w, w[1], o.w); o.w = fmaf(tr,  w[2], o.w);
    o.x = fmaf(ml,  w[3], o.x); o.x = fmaf(m.x, w[4], o.x); o.x = fmaf(m.y, w[5], o.x);
    o.y = fmaf(m.x, w[3], o.y); o.y = fmaf(m.y, w[4], o.y); o.y = fmaf(m.z, w[5], o.y);
    o.z = fmaf(m.y, w[3], o.z); o.z = fmaf(m.z, w[4], o.z); o.z = fmaf(m.w, w[5], o.z);
    o.w = fmaf(m.z, w[3], o.w); o.w = fmaf(m.w, w[4], o.w); o.w = fmaf(mr,  w[5], o.w);
    o.x = fmaf(bl,  w[6], o.x); o.x = fmaf(b.x, w[7], o.x); o.x = fmaf(b.y, w[8], o.x);
    o.y = fmaf(b.x, w[6], o.y); o.y = fmaf(b.y, w[7], o.y); o.y = fmaf(b.z, w[8], o.y);
    o.z = fmaf(b.y, w[6], o.z); o.z = fmaf(b.z, w[7], o.z); o.z = fmaf(b.w, w[8], o.z);
    o.w = fmaf(b.z, w[6], o.w); o.w = fmaf(b.w, w[7], o.w); o.w = fmaf(br,  w[8], o.w);
    return o;
}

// ---------------------------------------------------------------------------
// K1: TWO blocks per plane (half-planes of 64 rows). Each thread FRONT-LOADS
// its entire 10-row strip (10 independent LDG.128 back-to-back -> MLP=10,
// mean_kernel-style), then computes psum + conv sum/sumsq purely from regs.
// ---------------------------------------------------------------------------
__global__ void __launch_bounds__(256) stats_kernel(const float* __restrict__ x,
                                                     const float* __restrict__ rw) {
    int plane = blockIdx.x >> 1, half = blockIdx.x & 1;
    int c = plane & 255;
    int tid = threadIdx.x, lane = tid & 31, rseg = tid >> 5;
    int R0 = half * 64 + rseg * 8;
    const float4* xp = (const float4*)(x + (size_t)plane * HW);

    // Batched strip load: rows R0-1 .. R0+8 (halo rows zeroed at plane edges)
    float4 v[10];
    v[0] = (R0 == 0) ? zero4() : xp[(R0 - 1) * 32 + lane];
#pragma unroll
    for (int i = 1; i < 9; i++) v[i] = xp[(R0 - 1 + i) * 32 + lane];
    v[9] = (R0 + 8 > 127) ? zero4() : xp[(R0 + 8) * 32 + lane];

    float w[9];
#pragma unroll
    for (int i = 0; i < 9; i++) w[i] = rw[c * 9 + i];

    // psum over own rows R0..R0+7 = v[1..8]
    float psum = 0.f;
#pragma unroll
    for (int i = 1; i < 9; i++) psum += (v[i].x + v[i].y) + (v[i].z + v[i].w);

    // Rolling halo scalars (2 SHFL + 2 SEL per row, one row at a time)
    float l[3], r[3];
    l[0] = halo_l(v[0], lane); r[0] = halo_r(v[0], lane);
    l[1] = halo_l(v[1], lane); r[1] = halo_r(v[1], lane);

    float csum = 0.f, csq = 0.f;
#pragma unroll
    for (int i = 0; i < 8; i++) {
        l[(i + 2) % 3] = halo_l(v[i + 2], lane);
        r[(i + 2) % 3] = halo_r(v[i + 2], lane);
        float4 o = conv_row(v[i],     l[i % 3],       r[i % 3],
                            v[i + 1], l[(i + 1) % 3], r[(i + 1) % 3],
                            v[i + 2], l[(i + 2) % 3], r[(i + 2) % 3],
                            w, 0.f);
        csum += ((o.x + o.y) + (o.z + o.w));
        csq = fmaf(o.x, o.x, csq); csq = fmaf(o.y, o.y, csq);
        csq = fmaf(o.z, o.z, csq); csq = fmaf(o.w, o.w, csq);
    }

#pragma unroll
    for (int o = 16; o; o >>= 1) {
        psum += __shfl_xor_sync(FULL, psum, o);
        csum += __shfl_xor_sync(FULL, csum, o);
        csq  += __shfl_xor_sync(FULL, csq,  o);
    }
    __shared__ float r0[8], r1[8], r2[8];
    if (lane == 0) { r0[rseg] = psum; r1[rseg] = csum; r2[rseg] = csq; }
    __syncthreads();
    if (tid == 0) {
        float t0 = 0.f, t1 = 0.f, t2 = 0.f;
#pragma unroll
        for (int i = 0; i < 8; i++) { t0 += r0[i]; t1 += r1[i]; t2 += r2[i]; }
        int slot = half * NPLANES + plane;
        g_p[slot]  = t0;
        g_cs[slot] = t1;
        g_cq[slot] = t2;
    }
}

// ---------------------------------------------------------------------------
// K2 (fused SE attention): h = leaky(p @ w1^T); a = sigmoid(h @ w2^T).
// ---------------------------------------------------------------------------
__global__ void __launch_bounds__(256) attn_kernel(const float* __restrict__ w1,
                                                    const float* __restrict__ w2) {
    int b = blockIdx.x;
    __shared__ float ps[256];
    __shared__ float hs[64];
    int tid = threadIdx.x;
    int pl = b * 256 + tid;
    ps[tid] = (g_p[pl] + g_p[NPLANES + pl]) * (1.0f / 16384.0f);
    __syncthreads();
    {
        int j = tid >> 2, part = tid & 3;
        const float* wr = w1 + j * 256 + part * 64;
        const float* pr = ps + part * 64;
        float s = 0.f;
#pragma unroll
        for (int cc = 0; cc < 64; cc++) s = fmaf(pr[cc], wr[cc], s);
        s += __shfl_xor_sync(FULL, s, 1);
        s += __shfl_xor_sync(FULL, s, 2);
        if (part == 0) hs[j] = (s > 0.f) ? s : 0.01f * s;
    }
    __syncthreads();
    {
        const float* wr = w2 + tid * 64;
        float s = 0.f;
#pragma unroll
        for (int j = 0; j < 64; j++) s = fmaf(hs[j], wr[j], s);
        g_a[b * 256 + tid] = 1.0f / (1.0f + expf(-s));
    }
}

// ---------------------------------------------------------------------------
// K3: TWO blocks per plane (half-planes), reverse order (ride K1's L2 tail).
// Same front-batched 10-row strip. Conv with FULLY FOLDED weights:
// w' = a*rstd*w, init = (bias-mu)*rstd -> output already normalized;
// epilogue = leaky relu only. __ldcs reads (last use), __stcs stores.
// ---------------------------------------------------------------------------
__global__ void __launch_bounds__(256) main_kernel(const float* __restrict__ x,
                                                    const float* __restrict__ rw,
                                                    const float* __restrict__ rb,
                                                    float* __restrict__ out) {
    int idx = (2 * NPLANES - 1) - blockIdx.x;
    int bc = idx >> 1, half = idx & 1;
    int c = bc & 255;
    int tid = threadIdx.x, lane = tid & 31, rseg = tid >> 5;
    int R0 = half * 64 + rseg * 8;
    const float4* xp = (const float4*)(x + (size_t)bc * HW);
    float4* op = (float4*)(out + (size_t)bc * HW);

    // Batched strip load first (maximize outstanding loads)
    float4 v[10];
    v[0] = (R0 == 0) ? zero4() : __ldcs(xp + (R0 - 1) * 32 + lane);
#pragma unroll
    for (int i = 1; i < 9; i++) v[i] = __ldcs(xp + (R0 - 1 + i) * 32 + lane);
    v[9] = (R0 + 8 > 127) ? zero4() : __ldcs(xp + (R0 + 8) * 32 + lane);

    float a = g_a[bc];
    float bias = rb[c];
    float csum = g_cs[bc] + g_cs[NPLANES + bc];
    float csq  = g_cq[bc] + g_cq[NPLANES + bc];
    float mu_c  = csum * (1.0f / 16384.0f);
    float var_c = csq * (1.0f / 16384.0f) - mu_c * mu_c;
    float mu   = a * mu_c + bias;
    float rstd = rsqrtf(a * a * var_c + 1e-5f);
    float scale = a * rstd;
    float init = (bias - mu) * rstd;

    float w[9];
#pragma unroll
    for (int i = 0; i < 9; i++) w[i] = scale * rw[c * 9 + i];

    float l[3], r[3];
    l[0] = halo_l(v[0], lane); r[0] = halo_r(v[0], lane);
    l[1] = halo_l(v[1], lane); r[1] = halo_r(v[1], lane);

#pragma unroll
    for (int i = 0; i < 8; i++) {
        l[(i + 2) % 3] = halo_l(v[i + 2], lane);
        r[(i + 2) % 3] = halo_r(v[i + 2], lane);
        float4 o = conv_row(v[i],     l[i % 3],       r[i % 3],
                            v[i + 1], l[(i + 1) % 3], r[(i + 1) % 3],
                            v[i + 2], l[(i + 2) % 3], r[(i + 2) % 3],
                            w, init);                    // already normalized
        o.x = fmaxf(o.x, 0.01f * o.x);
        o.y = fmaxf(o.y, 0.01f * o.y);
        o.z = fmaxf(o.z, 0.01f * o.z);
        o.w = fmaxf(o.w, 0.01f * o.w);
        __stcs(op + (R0 + i) * 32 + lane, o);
    }
}

// ---------------------------------------------------------------------------
extern "C" void kernel_launch(void* const* d_in, const int* in_sizes, int n_in,
                              void* d_out, int out_size) {
    const float* x  = (const float*)d_in[0];
    const float* w1 = (const float*)d_in[1];   // [64, 256]
    const float* w2 = (const float*)d_in[2];   // [256, 64]
    const float* rw = (const float*)d_in[3];   // [256, 1, 3, 3]
    const float* rb = (const float*)d_in[4];   // [256]
    float* out = (float*)d_out;

    stats_kernel<<<2 * NPLANES, 256>>>(x, rw);
    attn_kernel<<<8, 256>>>(w1, w2);
    main_kernel<<<2 * NPLANES, 256>>>(x, rw, rb, out);
}